// round 7
// baseline (speedup 1.0000x reference)
#include <cuda_runtime.h>
#include <cstdint>
#include <cstddef>

#define BB 4096
#define TT 256
#define DD 64
#define HH 32

// 4096*256*32 floats = 134 MB scratch (device global; no runtime alloc)
__device__ float g_pre1[(size_t)BB * TT * HH];

// ---------- f32x2 helpers (sm_100+ packed fp32, 2x FFMA throughput) ----------
__device__ __forceinline__ unsigned long long f2pack(float lo, float hi) {
    unsigned long long r;
    asm("mov.b64 %0, {%1, %2};" : "=l"(r) : "f"(lo), "f"(hi));
    return r;
}
__device__ __forceinline__ unsigned long long fdup(float v) {
    unsigned long long r;
    asm("mov.b64 %0, {%1, %1};" : "=l"(r) : "f"(v));
    return r;
}
__device__ __forceinline__ unsigned long long ffma2(unsigned long long a,
                                                    unsigned long long b,
                                                    unsigned long long c) {
    unsigned long long d;
    asm("fma.rn.f32x2 %0, %1, %2, %3;" : "=l"(d) : "l"(a), "l"(b), "l"(c));
    return d;
}
__device__ __forceinline__ unsigned long long fadd2(unsigned long long a,
                                                    unsigned long long b) {
    unsigned long long d;
    asm("add.rn.f32x2 %0, %1, %2;" : "=l"(d) : "l"(a), "l"(b));
    return d;
}
__device__ __forceinline__ float2 f2unpack(unsigned long long v) {
    float lo, hi;
    asm("mov.b64 {%0, %1}, %2;" : "=f"(lo), "=f"(hi) : "l"(v));
    return make_float2(lo, hi);
}
__device__ __forceinline__ unsigned smem_u32(const void* p) {
    unsigned r;
    asm("{ .reg .u64 t; cvta.to.shared.u64 t, %1; cvt.u32.u64 %0, t; }"
        : "=r"(r) : "l"(p));
    return r;
}
// 16B shared load -> two f32x2 pairs (uniform addr => broadcast, 1 phase)
__device__ __forceinline__ void lds_v2u64(unsigned addr,
                                          unsigned long long& a,
                                          unsigned long long& b) {
    asm("ld.shared.v2.b64 {%0, %1}, [%2];" : "=l"(a), "=l"(b) : "r"(addr));
}

// =====================================================================
// Kernel 1: pre1[row][j] = b1[j] + sum_k states[row][k] * W1[k][j], k<64
// thread-per-(b,t)-row; warp stages 32 rows into padded smem
// (conflict-free 17-pad), W1 broadcast from smem as f32x2 pairs,
// 16 f32x2 accumulators per thread. Memory-bound (~402 MB).
// =====================================================================
__global__ __launch_bounds__(128) void k_pre1(const float* __restrict__ states,
                                              const float* __restrict__ W1,
                                              const float* __restrict__ b1) {
    __shared__ __align__(16) float4 s_tile[4][32][17];  // [warp][row][16 f4 + pad]
    __shared__ __align__(16) float  s_w1[DD * HH];      // W1 rows 0..63
    __shared__ __align__(16) float  s_b1[HH];

    const int tid = threadIdx.x, warp = tid >> 5, lane = tid & 31;

    for (int i = tid; i < DD * HH; i += 128) s_w1[i] = W1[i];
    if (tid < HH) s_b1[tid] = b1[tid];
    __syncthreads();

    const size_t rowBase = (size_t)blockIdx.x * 128 + (size_t)warp * 32;

    // stage 32 rows x 64 floats (512 float4), coalesced
    const float4* src = (const float4*)(states + rowBase * DD);
#pragma unroll
    for (int i = 0; i < 16; i++) {
        int x4 = i * 32 + lane;               // float4 index within tile
        s_tile[warp][x4 >> 4][x4 & 15] = src[x4];
    }
    __syncwarp();

    unsigned long long acc[16];
#pragma unroll
    for (int j = 0; j < 16; j++) acc[j] = 0ULL;

    const unsigned wbase = smem_u32(s_w1);

#pragma unroll 4
    for (int k4 = 0; k4 < 16; k4++) {
        float4 s4 = s_tile[warp][lane][k4];
        float sv[4] = {s4.x, s4.y, s4.z, s4.w};
#pragma unroll
        for (int kk = 0; kk < 4; kk++) {
            unsigned long long sd = fdup(sv[kk]);
            unsigned a = wbase + (unsigned)((k4 * 4 + kk) * HH * 4);
#pragma unroll
            for (int j8 = 0; j8 < 8; j8++) {
                unsigned long long p0, p1;
                lds_v2u64(a + j8 * 16, p0, p1);  // (W[k][4j8],W[k][4j8+1]),(+2,+3)
                acc[j8 * 2]     = ffma2(sd, p0, acc[j8 * 2]);
                acc[j8 * 2 + 1] = ffma2(sd, p1, acc[j8 * 2 + 1]);
            }
        }
    }

    float* dst = g_pre1 + (rowBase + (size_t)lane) * HH;
    const unsigned bbase = smem_u32(s_b1);
#pragma unroll
    for (int j8 = 0; j8 < 8; j8++) {
        unsigned long long q0, q1;
        lds_v2u64(bbase + j8 * 16, q0, q1);
        float2 a0 = f2unpack(fadd2(acc[j8 * 2],     q0));
        float2 a1 = f2unpack(fadd2(acc[j8 * 2 + 1], q1));
        float4 o;
        o.x = a0.x; o.y = a0.y; o.z = a1.x; o.w = a1.y;
        ((float4*)dst)[j8] = o;
    }
}

// =====================================================================
// Kernel 2: sequential scan over T. Warp-per-batch-row, lane = hidden dim.
// Per step: h1 = relu(pre1 + 4 indexed W1c rows); h2 = relu(h1@W2+b2);
// q = h2@W3+b3; argmax per 8-lane group of (q + gumbel) -> one-hot out
// (y_hard + y_soft - stop_grad(y_soft) == y_hard exactly; softmax and
// tau>0 are argmax-invariant).
// Matvecs: even/odd-k f32x2 partials, weight columns pinned in 64 regs.
// __launch_bounds__(128,4): 128-reg budget -> no spills; 4 warps/SMSP
// resident; per-step T = max(latency ~280, issue 4x~105) -> issue-bound.
// =====================================================================
__global__ __launch_bounds__(128, 4) void k_scan(const float* __restrict__ gumbel,
                                                 const float* __restrict__ W1,
                                                 const float* __restrict__ W2,
                                                 const float* __restrict__ b2v,
                                                 const float* __restrict__ W3,
                                                 const float* __restrict__ b3v,
                                                 float* __restrict__ out) {
    __shared__ __align__(16) float s_w1c[HH * HH];  // W1 rows 64..95
    __shared__ __align__(16) float s_h1[4][HH];
    __shared__ __align__(16) float s_h2[4][HH];

    const int tid = threadIdx.x, warp = tid >> 5, lane = tid & 31;

    for (int i = tid; i < HH * HH; i += 128) s_w1c[i] = W1[DD * HH + i];
    __syncthreads();

    // per-lane weight column, packed as (row 2i, row 2i+1) pairs: 64 regs total
    unsigned long long w2p[16], w3p[16];
#pragma unroll
    for (int i = 0; i < 16; i++) {
        w2p[i] = f2pack(W2[(2 * i) * HH + lane], W2[(2 * i + 1) * HH + lane]);
        w3p[i] = f2pack(W3[(2 * i) * HH + lane], W3[(2 * i + 1) * HH + lane]);
    }
    const float b2j = b2v[lane];
    const float b3j = b3v[lane];

    const size_t row = (size_t)blockIdx.x * 4 + (size_t)warp;
    const float* pre  = g_pre1 + row * TT * HH + lane;
    const float* gum  = gumbel + row * TT * HH + lane;
    float*       orow = out    + row * TT * HH + lane;

    const unsigned h1a = smem_u32(&s_h1[warp][0]);
    const unsigned h2a = smem_u32(&s_h2[warp][0]);

    const int myidx = lane & 7;
    int i0 = 0, i1 = 0, i2 = 0, i3 = 0;   // one-hot indices, init = one_hot(0)

    float preV = *pre;
    float gV   = *gum;

    for (int t = 0; t < TT; t++) {
        // prefetch next step (clamped offset, branch-free; 128B coalesced)
        const int stepOff = (t + 1 < TT) ? (t + 1) * HH : t * HH;
        const float preN = pre[stepOff];
        const float gN   = gum[stepOff];

        // ---- layer 1: pre1 + indexed rows of W1c, relu ----
        // i0..i3 are warp-uniform -> each LDS is a broadcast (1 phase)
        float h1 = preV
                 + s_w1c[(i0)      * HH + lane]
                 + s_w1c[(8  + i1) * HH + lane]
                 + s_w1c[(16 + i2) * HH + lane]
                 + s_w1c[(24 + i3) * HH + lane];
        h1 = fmaxf(h1, 0.0f);
        s_h1[warp][lane] = h1;
        __syncwarp();

        // ---- layer 2: h2[lane] = relu(b2 + sum_k h1[k]*W2[k][lane]) ----
        unsigned long long a0 = 0ULL, a1 = 0ULL;
#pragma unroll
        for (int i = 0; i < 8; i++) {
            unsigned long long p0, p1;
            lds_v2u64(h1a + i * 16, p0, p1);          // h1[4i..4i+3], broadcast
            a0 = ffma2(p0, w2p[2 * i],     a0);
            a1 = ffma2(p1, w2p[2 * i + 1], a1);
        }
        // pairwise combine: identical order to (x+x')+(y+y')
        float2 f = f2unpack(fadd2(a0, a1));
        float h2 = fmaxf(b2j + (f.x + f.y), 0.0f);
        s_h2[warp][lane] = h2;
        __syncwarp();

        // ---- layer 3: q[lane] = b3 + sum_k h2[k]*W3[k][lane] ----
        a0 = 0ULL; a1 = 0ULL;
#pragma unroll
        for (int i = 0; i < 8; i++) {
            unsigned long long p0, p1;
            lds_v2u64(h2a + i * 16, p0, p1);
            a0 = ffma2(p0, w3p[2 * i],     a0);
            a1 = ffma2(p1, w3p[2 * i + 1], a1);
        }
        f = f2unpack(fadd2(a0, a1));
        const float q = b3j + (f.x + f.y);

        // ---- gumbel + argmax per 8-lane group (first-index tie-break,
        //      matching jnp.argmax) ----
        const float v = q + gV;
        float bv = v; int bi = myidx;
#pragma unroll
        for (int d = 1; d < 8; d <<= 1) {
            float ov = __shfl_xor_sync(0xffffffffu, bv, d);
            int   oi = __shfl_xor_sync(0xffffffffu, bi, d);
            bool tk = (ov > bv) || (ov == bv && oi < bi);
            bv = tk ? ov : bv;
            bi = tk ? oi : bi;
        }

        // output = exact one-hot (y_hard; soft terms cancel bit-exactly)
        orow[t * HH] = (bi == myidx) ? 1.0f : 0.0f;

        // share the 4 group winners with every lane for the next step
        i0 = __shfl_sync(0xffffffffu, bi, 0);
        i1 = __shfl_sync(0xffffffffu, bi, 8);
        i2 = __shfl_sync(0xffffffffu, bi, 16);
        i3 = __shfl_sync(0xffffffffu, bi, 24);

        preV = preN; gV = gN;
    }
}

// =====================================================================
// Launch. Inputs per metadata order:
// 0 states, 1 gumbel, 2 tau (unused: >0 scalar, argmax-invariant),
// 3 W1, 4 b1, 5 W2, 6 b2, 7 W3, 8 b3
// =====================================================================
extern "C" void kernel_launch(void* const* d_in, const int* in_sizes, int n_in,
                              void* d_out, int out_size) {
    (void)in_sizes; (void)n_in; (void)out_size;
    const float* states = (const float*)d_in[0];
    const float* gumbel = (const float*)d_in[1];
    const float* W1     = (const float*)d_in[3];
    const float* b1     = (const float*)d_in[4];
    const float* W2     = (const float*)d_in[5];
    const float* b2     = (const float*)d_in[6];
    const float* W3     = (const float*)d_in[7];
    const float* b3     = (const float*)d_in[8];
    float* out = (float*)d_out;

    k_pre1<<<(BB * TT) / 128, 128>>>(states, W1, b1);
    k_scan<<<BB / 4, 128>>>(gumbel, W1, W2, b2, W3, b3, out);
}

// round 13
// speedup vs baseline: 1.1135x; 1.1135x over previous
#include <cuda_runtime.h>
#include <cstdint>
#include <cstddef>

#define BB 4096
#define TT 256
#define DD 64
#define HH 32

// 4096*256*32 floats = 134 MB scratch (device global; no runtime alloc)
__device__ float g_pre1[(size_t)BB * TT * HH];

// ---------- f32x2 helpers (sm_100+ packed fp32, 2x FFMA throughput) ----------
__device__ __forceinline__ unsigned long long f2pack(float lo, float hi) {
    unsigned long long r;
    asm("mov.b64 %0, {%1, %2};" : "=l"(r) : "f"(lo), "f"(hi));
    return r;
}
__device__ __forceinline__ unsigned long long fdup(float v) {
    unsigned long long r;
    asm("mov.b64 %0, {%1, %1};" : "=l"(r) : "f"(v));
    return r;
}
__device__ __forceinline__ unsigned long long ffma2(unsigned long long a,
                                                    unsigned long long b,
                                                    unsigned long long c) {
    unsigned long long d;
    asm("fma.rn.f32x2 %0, %1, %2, %3;" : "=l"(d) : "l"(a), "l"(b), "l"(c));
    return d;
}
__device__ __forceinline__ unsigned long long fadd2(unsigned long long a,
                                                    unsigned long long b) {
    unsigned long long d;
    asm("add.rn.f32x2 %0, %1, %2;" : "=l"(d) : "l"(a), "l"(b));
    return d;
}
__device__ __forceinline__ float2 f2unpack(unsigned long long v) {
    float lo, hi;
    asm("mov.b64 {%0, %1}, %2;" : "=f"(lo), "=f"(hi) : "l"(v));
    return make_float2(lo, hi);
}
__device__ __forceinline__ unsigned smem_u32(const void* p) {
    unsigned r;
    asm("{ .reg .u64 t; cvta.to.shared.u64 t, %1; cvt.u32.u64 %0, t; }"
        : "=r"(r) : "l"(p));
    return r;
}
// 16B shared load -> two f32x2 pairs.
// MUST be volatile + "memory": without it the compiler may hoist these
// loads across the C++ stores of h1/h2 and across __syncwarp (no declared
// memory dependency) -> stale values. This was the R8 correctness failure.
__device__ __forceinline__ void lds_v2u64(unsigned addr,
                                          unsigned long long& a,
                                          unsigned long long& b) {
    asm volatile("ld.shared.v2.b64 {%0, %1}, [%2];"
                 : "=l"(a), "=l"(b) : "r"(addr) : "memory");
}

// =====================================================================
// Kernel 1: pre1[row][j] = b1[j] + sum_k states[row][k] * W1[k][j], k<64
// thread-per-(b,t)-row; warp stages 32 rows into padded smem, weights
// broadcast as f32x2 pairs. Output staged back through smem so the
// global stores are lane-coalesced 512B (was: 32 lines per STG.128).
// =====================================================================
__global__ __launch_bounds__(128) void k_pre1(const float* __restrict__ states,
                                              const float* __restrict__ W1,
                                              const float* __restrict__ b1) {
    __shared__ __align__(16) float4 s_tile[4][32][17];  // [warp][row][16 f4 + pad]
    __shared__ __align__(16) float  s_w1[DD * HH];      // W1 rows 0..63
    __shared__ __align__(16) float  s_b1[HH];

    const int tid = threadIdx.x, warp = tid >> 5, lane = tid & 31;

    for (int i = tid; i < DD * HH; i += 128) s_w1[i] = W1[i];
    if (tid < HH) s_b1[tid] = b1[tid];
    __syncthreads();

    const size_t rowBase = (size_t)blockIdx.x * 128 + (size_t)warp * 32;

    // stage 32 rows x 64 floats (512 float4), coalesced
    const float4* src = (const float4*)(states + rowBase * DD);
#pragma unroll
    for (int i = 0; i < 16; i++) {
        int x4 = i * 32 + lane;               // float4 index within tile
        s_tile[warp][x4 >> 4][x4 & 15] = src[x4];
    }
    __syncwarp();

    unsigned long long acc[16];
#pragma unroll
    for (int j = 0; j < 16; j++) acc[j] = 0ULL;

    const unsigned wbase = smem_u32(s_w1);

#pragma unroll 4
    for (int k4 = 0; k4 < 16; k4++) {
        float4 s4 = s_tile[warp][lane][k4];
        float sv[4] = {s4.x, s4.y, s4.z, s4.w};
#pragma unroll
        for (int kk = 0; kk < 4; kk++) {
            unsigned long long sd = fdup(sv[kk]);
            unsigned a = wbase + (unsigned)((k4 * 4 + kk) * HH * 4);
#pragma unroll
            for (int j8 = 0; j8 < 8; j8++) {
                unsigned long long p0, p1;
                lds_v2u64(a + j8 * 16, p0, p1);  // (W[k][4j8],W[k][4j8+1]),(+2,+3)
                acc[j8 * 2]     = ffma2(sd, p0, acc[j8 * 2]);
                acc[j8 * 2 + 1] = ffma2(sd, p1, acc[j8 * 2 + 1]);
            }
        }
    }

    // ---- stage result into this thread's (fully consumed) tile row ----
    const unsigned bbase = smem_u32(s_b1);
#pragma unroll
    for (int j8 = 0; j8 < 8; j8++) {
        unsigned long long q0, q1;
        lds_v2u64(bbase + j8 * 16, q0, q1);
        float2 a0 = f2unpack(fadd2(acc[j8 * 2],     q0));
        float2 a1 = f2unpack(fadd2(acc[j8 * 2 + 1], q1));
        float4 o;
        o.x = a0.x; o.y = a0.y; o.z = a1.x; o.w = a1.y;
        s_tile[warp][lane][j8] = o;
    }
    __syncwarp();

    // ---- cooperative coalesced store: 256 float4 (32 rows x 8 f4) ----
    float4* dst4 = (float4*)(g_pre1 + rowBase * HH);
#pragma unroll
    for (int i = 0; i < 8; i++) {
        int x4 = i * 32 + lane;               // 0..255
        dst4[x4] = s_tile[warp][x4 >> 3][x4 & 7];
    }
}

// =====================================================================
// Kernel 2: sequential scan over T. Warp-per-batch-row, lane = hidden dim.
// vs R7 measurement (latency-bound: issue 28.5%, occ 21%, ~1475 cyc/step
// dominated by per-step DRAM loads):
//  - prefetch distance 4 (rotating buffers, unroll-4) hides LDG latency
//  - W3 columns in conflict-free chunked smem instead of 32 pinned regs
//    -> __launch_bounds__(128,5) -> 5 blocks/SM (occ ~31%)
// =====================================================================
__global__ __launch_bounds__(128, 5) void k_scan(const float* __restrict__ gumbel,
                                                 const float* __restrict__ W1,
                                                 const float* __restrict__ W2,
                                                 const float* __restrict__ b2v,
                                                 const float* __restrict__ W3,
                                                 const float* __restrict__ b3v,
                                                 float* __restrict__ out) {
    __shared__ __align__(16) float s_w1c[HH * HH];      // W1 rows 64..95
    __shared__ __align__(16) float s_w3c[8][HH][4];     // W3[4i+kk][j] chunks
    __shared__ __align__(16) float s_h1[4][HH];
    __shared__ __align__(16) float s_h2[4][HH];

    const int tid = threadIdx.x, warp = tid >> 5, lane = tid & 31;

    for (int i = tid; i < HH * HH; i += 128) s_w1c[i] = W1[DD * HH + i];
    // W3 chunked: s_w3c[i][j][kk] = W3[(4i+kk)*HH + j]
    for (int idx = tid; idx < 8 * HH * 4; idx += 128) {
        int ci = idx >> 7, rem = idx & 127, j = rem >> 2, kk = rem & 3;
        s_w3c[ci][j][kk] = W3[(4 * ci + kk) * HH + j];
    }
    __syncthreads();

    // W2 columns stay pinned: (row 2i, row 2i+1) pairs, 32 regs
    unsigned long long w2p[16];
#pragma unroll
    for (int i = 0; i < 16; i++)
        w2p[i] = f2pack(W2[(2 * i) * HH + lane], W2[(2 * i + 1) * HH + lane]);
    const float b2j = b2v[lane];
    const float b3j = b3v[lane];

    const size_t row = (size_t)blockIdx.x * 4 + (size_t)warp;
    const float* pre  = g_pre1 + row * TT * HH + lane;
    const float* gum  = gumbel + row * TT * HH + lane;
    float*       orow = out    + row * TT * HH + lane;

    const unsigned h1a = smem_u32(&s_h1[warp][0]);
    const unsigned h2a = smem_u32(&s_h2[warp][0]);
    const unsigned w3a = smem_u32(&s_w3c[0][lane][0]);  // +i*512 per chunk

    const int myidx = lane & 7;
    int i0 = 0, i1 = 0, i2 = 0, i3 = 0;   // one-hot indices, init = one_hot(0)

    // prefetch pipeline, distance 4
    float pB[4], gB[4];
#pragma unroll
    for (int u = 0; u < 4; u++) { pB[u] = pre[u * HH]; gB[u] = gum[u * HH]; }

    for (int t = 0; t < TT; t += 4) {
#pragma unroll
        for (int u = 0; u < 4; u++) {
            const float preV = pB[u];
            const float gV   = gB[u];
            // issue next prefetch (consumed 4 steps from now)
            int tn = t + 4 + u; tn = (tn < TT) ? tn : (TT - 1);
            pB[u] = pre[tn * HH];
            gB[u] = gum[tn * HH];

            // ---- layer 1: pre1 + indexed rows of W1c, relu ----
            float h1 = preV
                     + s_w1c[(i0)      * HH + lane]
                     + s_w1c[(8  + i1) * HH + lane]
                     + s_w1c[(16 + i2) * HH + lane]
                     + s_w1c[(24 + i3) * HH + lane];
            h1 = fmaxf(h1, 0.0f);
            s_h1[warp][lane] = h1;
            __syncwarp();

            // ---- layer 2: h2 = relu(b2 + h1 @ W2[:,lane]) ----
            unsigned long long a0 = 0ULL, a1 = 0ULL;
#pragma unroll
            for (int i = 0; i < 8; i++) {
                unsigned long long p0, p1;
                lds_v2u64(h1a + i * 16, p0, p1);      // h1[4i..4i+3] broadcast
                a0 = ffma2(p0, w2p[2 * i],     a0);
                a1 = ffma2(p1, w2p[2 * i + 1], a1);
            }
            float2 f = f2unpack(fadd2(a0, a1));
            float h2 = fmaxf(b2j + (f.x + f.y), 0.0f);
            s_h2[warp][lane] = h2;
            __syncwarp();

            // ---- layer 3: q = b3 + h2 @ W3[:,lane] (W3 from smem) ----
            a0 = 0ULL; a1 = 0ULL;
#pragma unroll
            for (int i = 0; i < 8; i++) {
                unsigned long long p0, p1, w01, w23;
                lds_v2u64(h2a + i * 16, p0, p1);      // broadcast
                lds_v2u64(w3a + i * 512, w01, w23);   // per-lane, conflict-free
                a0 = ffma2(p0, w01, a0);
                a1 = ffma2(p1, w23, a1);
            }
            f = f2unpack(fadd2(a0, a1));
            const float q = b3j + (f.x + f.y);

            // ---- gumbel + argmax per 8-lane group (first-index tie-break) ----
            const float v = q + gV;
            float bv = v; int bi = myidx;
#pragma unroll
            for (int d = 1; d < 8; d <<= 1) {
                float ov = __shfl_xor_sync(0xffffffffu, bv, d);
                int   oi = __shfl_xor_sync(0xffffffffu, bi, d);
                bool tk = (ov > bv) || (ov == bv && oi < bi);
                bv = tk ? ov : bv;
                bi = tk ? oi : bi;
            }

            // output = exact one-hot (y_hard; soft terms cancel bit-exactly)
            orow[(t + u) * HH] = (bi == myidx) ? 1.0f : 0.0f;

            // share the 4 group winners with every lane for the next step
            i0 = __shfl_sync(0xffffffffu, bi, 0);
            i1 = __shfl_sync(0xffffffffu, bi, 8);
            i2 = __shfl_sync(0xffffffffu, bi, 16);
            i3 = __shfl_sync(0xffffffffu, bi, 24);
        }
    }
}

// =====================================================================
// Launch. Inputs per metadata order:
// 0 states, 1 gumbel, 2 tau (unused: >0 scalar, argmax-invariant),
// 3 W1, 4 b1, 5 W2, 6 b2, 7 W3, 8 b3
// =====================================================================
extern "C" void kernel_launch(void* const* d_in, const int* in_sizes, int n_in,
                              void* d_out, int out_size) {
    (void)in_sizes; (void)n_in; (void)out_size;
    const float* states = (const float*)d_in[0];
    const float* gumbel = (const float*)d_in[1];
    const float* W1     = (const float*)d_in[3];
    const float* b1     = (const float*)d_in[4];
    const float* W2     = (const float*)d_in[5];
    const float* b2     = (const float*)d_in[6];
    const float* W3     = (const float*)d_in[7];
    const float* b3     = (const float*)d_in[8];
    float* out = (float*)d_out;

    k_pre1<<<(BB * TT) / 128, 128>>>(states, W1, b1);
    k_scan<<<BB / 4, 128>>>(gumbel, W1, W2, b2, W3, b3, out);
}